// round 9
// baseline (speedup 1.0000x reference)
#include <cuda_runtime.h>
#include <cstdint>

// Problem constants
#define BB    8
#define PNN   16384
#define NSS   256
#define KDIMC 512
#define HIDC  384
#define HALFC 192
#define CIN1  576            // HID + HALF
#define MROWS (BB*NSS)       // 2048
#define EPSC  1e-5f

// ---------------- scratch (device globals; no allocation allowed) ----------
__device__ float               g_L[6];                 // chol(G)
__device__ __align__(16) float g_gf[BB*HIDC];
__device__ int                 g_sel[BB*NSS];
__device__ __align__(16) float4 g_pts[BB*PNN];         // reordered u-coords
__device__ int                 g_oidx[BB*PNN];
__device__ __align__(16) float g_comb[MROWS*CIN1];
__device__ __align__(16) float g_h1[MROWS*HIDC];
__device__ __align__(16) float g_h2[MROWS*HIDC];
__device__ __align__(16) float g_sc1[HIDC];
__device__ __align__(16) float g_sh1[HIDC];
__device__ __align__(16) float g_sc2[HIDC];
__device__ __align__(16) float g_sh2[HIDC];

// ---------------- helpers ---------------------------------------------------
__device__ __forceinline__ unsigned fenc(float f){
    unsigned u = __float_as_uint(f);
    return u ^ (unsigned)(((int)u >> 31) | 0x80000000);
}
__device__ __forceinline__ float fdec(unsigned u){
    unsigned b = (u & 0x80000000u) ? (u ^ 0x80000000u) : ~u;
    return __uint_as_float(b);
}
__device__ __forceinline__ int morton3(int x, int y, int z){
    int m = 0;
#pragma unroll
    for (int i = 0; i < 3; i++)
        m |= ((x>>i&1)<<(3*i+2)) | ((y>>i&1)<<(3*i+1)) | ((z>>i&1)<<(3*i));
    return m;
}
__device__ __forceinline__ unsigned long long pk2(float lo, float hi){
    unsigned long long r;
    asm("mov.b64 %0, {%1, %2};" : "=l"(r) : "f"(lo), "f"(hi));
    return r;
}
__device__ __forceinline__ void upk2(unsigned long long v, float& lo, float& hi){
    asm("mov.b64 {%0, %1}, %2;" : "=f"(lo), "=f"(hi) : "l"(v));
}
__device__ __forceinline__ unsigned long long fma2(unsigned long long a,
                                                   unsigned long long b,
                                                   unsigned long long c){
    unsigned long long r;
    asm("fma.rn.f32x2 %0, %1, %2, %3;" : "=l"(r) : "l"(a), "l"(b), "l"(c));
    return r;
}
__device__ __forceinline__ unsigned long long add2(unsigned long long a,
                                                   unsigned long long b){
    unsigned long long r;
    asm("add.rn.f32x2 %0, %1, %2;" : "=l"(r) : "l"(a), "l"(b));
    return r;
}
__device__ __forceinline__ unsigned long long mul2(unsigned long long a,
                                                   unsigned long long b){
    unsigned long long r;
    asm("mul.rn.f32x2 %0, %1, %2;" : "=l"(r) : "l"(a), "l"(b));
    return r;
}
// try_wait + cluster acquire (pairs with peer's arrive.release.cluster)
__device__ __forceinline__ void mbar_wait_cl(uint32_t addr, unsigned parity){
    unsigned done;
    do {
        asm volatile(
            "{\n\t.reg .pred p;\n\t"
            "mbarrier.try_wait.parity.acquire.cluster.shared::cta.b64 p, [%1], %2, 0x989680;\n\t"
            "selp.b32 %0, 1, 0, p;\n\t}"
            : "=r"(done) : "r"(addr), "r"(parity) : "memory");
    } while(!done);
}

// ---------------- G = Wc @ Wc^T, then Cholesky ------------------------------
__global__ void k_gram(const float* __restrict__ Wc){
    __shared__ float sG[9];
    const int pa[6] = {0,0,0,1,1,2};
    const int pb[6] = {0,1,2,1,2,2};
    int w = threadIdx.x >> 5, lane = threadIdx.x & 31;
    if (w < 6){
        float s = 0.f;
        for (int k = lane; k < HALFC; k += 32)
            s = fmaf(Wc[pa[w]*HALFC + k], Wc[pb[w]*HALFC + k], s);
#pragma unroll
        for (int o = 16; o > 0; o >>= 1) s += __shfl_down_sync(0xffffffffu, s, o);
        if (lane == 0){ sG[pa[w]*3+pb[w]] = s; sG[pb[w]*3+pa[w]] = s; }
    }
    __syncthreads();
    if (threadIdx.x == 0){
        float G00=sG[0],G01=sG[1],G02=sG[2],G11=sG[4],G12=sG[5],G22=sG[8];
        float L00 = sqrtf(G00);
        float L10 = G01 / L00;
        float L20 = G02 / L00;
        float L11 = sqrtf(G11 - L10*L10);
        float L21 = (G12 - L10*L20) / L11;
        float L22 = sqrtf(G22 - L20*L20 - L21*L21);
        g_L[0]=L00; g_L[1]=L10; g_L[2]=L20; g_L[3]=L11; g_L[4]=L21; g_L[5]=L22;
    }
}

// ---------------- global_feat = pf @ W_feat + b_feat  (8 x 384) ------------
__global__ void k_gf(const float* __restrict__ pf, const float* __restrict__ Wf,
                     const float* __restrict__ bf){
    __shared__ float sp[KDIMC];
    int b = blockIdx.x, t = threadIdx.x;
    for (int k = t; k < KDIMC; k += blockDim.x) sp[k] = pf[b*KDIMC + k];
    __syncthreads();
    float acc = bf[t];
#pragma unroll 4
    for (int k = 0; k < KDIMC; k++)
        acc = fmaf(sp[k], Wf[k*HIDC + t], acc);
    g_gf[b*HIDC + t] = acc;
}

// ---------------- k_prep: u = L^T p, Morton counting sort ------------------
__global__ __launch_bounds__(1024) void k_prep(const float* __restrict__ P){
    __shared__ unsigned s_bb[6];
    __shared__ int s_hist[512];
    __shared__ int s_off[512];
    __shared__ int s_wsum[16];
    __shared__ float s_lo[3], s_iv[3];

    int b = blockIdx.x, t = threadIdx.x;
    int lane = t & 31;
    float L00=g_L[0],L10=g_L[1],L20=g_L[2],L11=g_L[3],L21=g_L[4],L22=g_L[5];
    const float* pb = P + (size_t)b*PNN*3;

    if (t < 3)            s_bb[t] = 0xFFFFFFFFu;
    else if (t < 6)       s_bb[t] = 0u;
    if (t < 512) s_hist[t] = 0;
    __syncthreads();

    float mn[3] = {1e30f,1e30f,1e30f}, mx[3] = {-1e30f,-1e30f,-1e30f};
#pragma unroll
    for (int k = 0; k < 16; k++){
        int idx = t + k*1024;
        float px=pb[idx*3+0], py=pb[idx*3+1], pz=pb[idx*3+2];
        float u0 = fmaf(L00,px, fmaf(L10,py, L20*pz));
        float u1 = fmaf(L11,py, L21*pz);
        float u2 = L22*pz;
        mn[0]=fminf(mn[0],u0); mx[0]=fmaxf(mx[0],u0);
        mn[1]=fminf(mn[1],u1); mx[1]=fmaxf(mx[1],u1);
        mn[2]=fminf(mn[2],u2); mx[2]=fmaxf(mx[2],u2);
    }
#pragma unroll
    for (int d = 0; d < 3; d++){
        unsigned emn = __reduce_min_sync(0xffffffffu, fenc(mn[d]));
        unsigned emx = __reduce_max_sync(0xffffffffu, fenc(mx[d]));
        if (lane == 0){ atomicMin(&s_bb[d], emn); atomicMax(&s_bb[3+d], emx); }
    }
    __syncthreads();
    if (t < 3){
        float lo = fdec(s_bb[t]), hi = fdec(s_bb[3+t]);
        s_lo[t] = lo;
        s_iv[t] = 8.0f / fmaxf(hi - lo, 1e-20f);
    }
    __syncthreads();

    float lo0=s_lo[0], lo1=s_lo[1], lo2=s_lo[2];
    float iv0=s_iv[0], iv1=s_iv[1], iv2=s_iv[2];
    int cell[16];
#pragma unroll
    for (int k = 0; k < 16; k++){
        int idx = t + k*1024;
        float px=pb[idx*3+0], py=pb[idx*3+1], pz=pb[idx*3+2];
        float u0 = fmaf(L00,px, fmaf(L10,py, L20*pz));
        float u1 = fmaf(L11,py, L21*pz);
        float u2 = L22*pz;
        int c0 = min(7, max(0, (int)((u0-lo0)*iv0)));
        int c1 = min(7, max(0, (int)((u1-lo1)*iv1)));
        int c2 = min(7, max(0, (int)((u2-lo2)*iv2)));
        cell[k] = morton3(c0, c1, c2);
        atomicAdd(&s_hist[cell[k]], 1);
    }
    __syncthreads();

    if (t < 512){
        int v = s_hist[t], inc = v;
#pragma unroll
        for (int o = 1; o < 32; o <<= 1){
            int n = __shfl_up_sync(0xffffffffu, inc, o);
            if (lane >= o) inc += n;
        }
        if (lane == 31) s_wsum[t >> 5] = inc;
        s_off[t] = inc - v;
    }
    __syncthreads();
    if (t < 16){
        int v = s_wsum[t], inc = v;
#pragma unroll
        for (int o = 1; o < 16; o <<= 1){
            int n = __shfl_up_sync(0xffffu, inc, o);
            if (t >= o) inc += n;
        }
        s_wsum[t] = inc - v;
    }
    __syncthreads();
    if (t < 512) s_off[t] += s_wsum[t >> 5];
    __syncthreads();

#pragma unroll
    for (int k = 0; k < 16; k++){
        int idx = t + k*1024;
        float px=pb[idx*3+0], py=pb[idx*3+1], pz=pb[idx*3+2];
        float u0 = fmaf(L00,px, fmaf(L10,py, L20*pz));
        float u1 = fmaf(L11,py, L21*pz);
        float u2 = L22*pz;
        int pos = atomicAdd(&s_off[cell[k]], 1);
        g_pts[b*PNN + pos]  = make_float4(u0, u1, u2, 0.f);
        g_oidx[b*PNN + pos] = idx;
    }
}

// ---------------- FPS v6b: 2-CTA cluster/batch, all-register state ---------
// Same as round-8 design with the exchange word-order bug fixed: the u64 key
// store puts gl in the LOW word ([0]) and gh in the HIGH word ([1]); reads now
// match (pl=[0], ph=[1]).
#define FPS_T   1024
#define HALF_P  (PNN/2)     // 8192 points per CTA
#define KPT     8

__global__ void __cluster_dims__(2,1,1) __launch_bounds__(FPS_T,1)
k_fps6(const float* __restrict__ P)
{
    __shared__ float slot[32*9];                 // hi,lo,x,y,z (stride 9)
    __shared__ __align__(8) unsigned long long s_mbar;
    __shared__ __align__(8) unsigned ex[2][6];   // peer-written: [0]=gl,[1]=gh,[2]=x,[3]=y,[4]=z
    __shared__ float bcast[4];
    __shared__ int s_oidx[HALF_P];

    const int t = threadIdx.x, lane = t & 31, wid = t >> 5;
    const int rank = blockIdx.x & 1;
    const int b    = blockIdx.x >> 1;
    const int base = rank * HALF_P;
    const float4* gp = g_pts + (size_t)b*PNN;

    uint32_t mbar_addr = (uint32_t)__cvta_generic_to_shared(&s_mbar);
    uint32_t ex_addr   = (uint32_t)__cvta_generic_to_shared(&ex[0][0]);
    uint32_t peer_mbar, peer_ex;
    asm volatile("mapa.shared::cluster.u32 %0, %1, %2;"
                 : "=r"(peer_mbar) : "r"(mbar_addr), "r"(rank ^ 1));
    asm volatile("mapa.shared::cluster.u32 %0, %1, %2;"
                 : "=r"(peer_ex) : "r"(ex_addr), "r"(rank ^ 1));

    if (t == 0){
        asm volatile("mbarrier.init.shared.b64 [%0], %1;"
                     :: "r"(mbar_addr), "r"(1) : "memory");
    }

    // oidx into smem (extraction-time lookups)
    for (int r = t; r < HALF_P; r += FPS_T)
        s_oidx[r] = g_oidx[b*PNN + base + r];

    // my 8 points -> packed registers; warp box
    unsigned long long X2[4], Y2[4], Z2[4];
    float d[KPT];
    float bl0=1e30f, bl1=1e30f, bl2=1e30f, bh0=-1e30f, bh1=-1e30f, bh2=-1e30f;
#pragma unroll
    for (int i = 0; i < 4; i++){
        float4 v0 = gp[base + t*KPT + 2*i];
        float4 v1 = gp[base + t*KPT + 2*i + 1];
        X2[i] = pk2(v0.x, v1.x); Y2[i] = pk2(v0.y, v1.y); Z2[i] = pk2(v0.z, v1.z);
        d[2*i] = 1e10f; d[2*i+1] = 1e10f;
        bl0=fminf(bl0,fminf(v0.x,v1.x)); bh0=fmaxf(bh0,fmaxf(v0.x,v1.x));
        bl1=fminf(bl1,fminf(v0.y,v1.y)); bh1=fmaxf(bh1,fmaxf(v0.y,v1.y));
        bl2=fminf(bl2,fminf(v0.z,v1.z)); bh2=fmaxf(bh2,fmaxf(v0.z,v1.z));
    }
    bl0 = fdec(__reduce_min_sync(0xffffffffu, fenc(bl0)));
    bl1 = fdec(__reduce_min_sync(0xffffffffu, fenc(bl1)));
    bl2 = fdec(__reduce_min_sync(0xffffffffu, fenc(bl2)));
    bh0 = fdec(__reduce_max_sync(0xffffffffu, fenc(bh0)));
    bh1 = fdec(__reduce_max_sync(0xffffffffu, fenc(bh1)));
    bh2 = fdec(__reduce_max_sync(0xffffffffu, fenc(bh2)));

    // first centroid = ORIGINAL point 0 (uniform broadcast compute)
    const float* p0 = P + (size_t)b*PNN*3;
    float px0=p0[0], py0=p0[1], pz0=p0[2];
    float cx = fmaf(g_L[0],px0, fmaf(g_L[1],py0, g_L[2]*pz0));
    float cy = fmaf(g_L[3],py0, g_L[4]*pz0);
    float cz = g_L[5]*pz0;
    if (rank == 0 && t == 0) g_sel[b*NSS] = 0;

    // mbar init visible cluster-wide before any cross-CTA arrive
    asm volatile("barrier.cluster.arrive.aligned;\n\t"
                 "barrier.cluster.wait.aligned;" ::: "memory");
    __syncthreads();

    unsigned wub   = 0xFFFFFFFFu;   // forces first update
    unsigned phase = 0;

    for (int j = 0; j < NSS-1; j++){
        float e0 = fmaxf(fmaxf(bl0-cx, cx-bh0), 0.f);
        float e1 = fmaxf(fmaxf(bl1-cy, cy-bh1), 0.f);
        float e2 = fmaxf(fmaxf(bl2-cz, cz-bh2), 0.f);
        float lb = fmaf(e0,e0, fmaf(e1,e1, e2*e2));

        if (__float_as_uint(lb) < wub){
            unsigned long long mcx2 = pk2(-cx,-cx);
            unsigned long long mcy2 = pk2(-cy,-cy);
            unsigned long long mcz2 = pk2(-cz,-cz);
#pragma unroll
            for (int i = 0; i < 4; i++){
                unsigned long long ax = add2(X2[i], mcx2);
                unsigned long long ay = add2(Y2[i], mcy2);
                unsigned long long az = add2(Z2[i], mcz2);
                unsigned long long dd = fma2(ax,ax, fma2(ay,ay, mul2(az,az)));
                float d0, d1; upk2(dd, d0, d1);
                d[2*i]   = fminf(d[2*i],   d0);
                d[2*i+1] = fminf(d[2*i+1], d1);
            }
            float ub = fmaxf(fmaxf(fmaxf(d[0],d[1]), fmaxf(d[2],d[3])),
                             fmaxf(fmaxf(d[4],d[5]), fmaxf(d[6],d[7])));
            wub = __reduce_max_sync(0xffffffffu, __float_as_uint(ub));

            // candidate: tying lanes look up oidx and pack (~oidx<<13 | r)
            unsigned cand = 0u; int kw = 0;
            if (__float_as_uint(ub) == wub){
#pragma unroll
                for (int k = 0; k < KPT; k++){
                    if (__float_as_uint(d[k]) == wub){
                        unsigned r = (unsigned)(t*KPT + k);
                        unsigned c = ((0x3FFFu - (unsigned)s_oidx[r]) << 13) | r;
                        if (c > cand){ cand = c; kw = k; }
                    }
                }
            }
            unsigned wlo = __reduce_max_sync(0xffffffffu, cand);
            if (cand == wlo && cand != 0u){
                float sx, sy, sz, tmp;
                if (kw & 1){ upk2(X2[kw>>1], tmp, sx); upk2(Y2[kw>>1], tmp, sy); upk2(Z2[kw>>1], tmp, sz); }
                else       { upk2(X2[kw>>1], sx, tmp); upk2(Y2[kw>>1], sy, tmp); upk2(Z2[kw>>1], sz, tmp); }
                slot[wid*9+0] = __uint_as_float(wub);
                slot[wid*9+1] = __uint_as_float(wlo);
                slot[wid*9+2] = sx; slot[wid*9+3] = sy; slot[wid*9+4] = sz;
            }
        }
        __syncthreads();                          // bar1

        // block reduce over 32 warp slots (all warps redundantly)
        unsigned hi = __float_as_uint(slot[lane*9+0]);
        unsigned lo = __float_as_uint(slot[lane*9+1]);
        unsigned gh = __reduce_max_sync(0xffffffffu, hi);
        unsigned gl = __reduce_max_sync(0xffffffffu, (hi==gh) ? lo : 0u);

        if (t == 0){
            int w = (int)((gl & 0x1FFFu) >> 8);   // r -> warp (256 pts/warp)
            float sx = slot[w*9+2], sy = slot[w*9+3], sz = slot[w*9+4];
            // send (key, coords) into peer's ex[j&1]
            unsigned eoff = (unsigned)(j & 1) * 24u;
            unsigned long long k64 = ((unsigned long long)gh << 32) | gl;
            asm volatile("st.shared::cluster.u64 [%0], %1;"
                         :: "r"(peer_ex + eoff), "l"(k64) : "memory");       // [0]=gl, [1]=gh
            asm volatile("st.shared::cluster.u64 [%0], %1;"
                         :: "r"(peer_ex + eoff + 8), "l"(pk2(sx, sy)) : "memory"); // [2]=x,[3]=y
            asm volatile("st.shared::cluster.u32 [%0], %1;"
                         :: "r"(peer_ex + eoff + 16), "r"(__float_as_uint(sz)) : "memory"); // [4]=z
            asm volatile("mbarrier.arrive.release.cluster.shared::cluster.b64 _, [%0];"
                         :: "r"(peer_mbar) : "memory");
            mbar_wait_cl(mbar_addr, phase);
            unsigned pl = ex[j&1][0], ph = ex[j&1][1];   // FIX: [0]=low(gl), [1]=high(gh)
            if (ph > gh || (ph == gh && pl > gl)){
                gh = ph; gl = pl;
                sx = __uint_as_float(ex[j&1][2]);
                sy = __uint_as_float(ex[j&1][3]);
                sz = __uint_as_float(ex[j&1][4]);
            }
            bcast[0] = sx; bcast[1] = sy; bcast[2] = sz;
            if (rank == 0) g_sel[b*NSS + j + 1] = (int)(0x3FFFu - (gl >> 13));
        }
        __syncthreads();                          // bar2
        cx = bcast[0]; cy = bcast[1]; cz = bcast[2];
        phase ^= 1;
    }
    // peer may still access my SMEM
    asm volatile("barrier.cluster.arrive.aligned;\n\t"
                 "barrier.cluster.wait.aligned;" ::: "memory");
}

// ---------------- build combined (2048 x 576), float4-flat -----------------
__global__ __launch_bounds__(256) void k_comb(const float* __restrict__ P,
                                              const float* __restrict__ Wc,
                                              const float* __restrict__ bc){
    int f = blockIdx.x * 256 + threadIdx.x;
    int n = f / 144, c4 = f % 144;
    int b = n >> 8;
    if (c4 < 96){
        float4 v = *(const float4*)&g_gf[b*HIDC + c4*4];
        *(float4*)&g_comb[(size_t)n*CIN1 + c4*4] = v;
    } else {
        int o = (c4 - 96) * 4;
        int sidx = g_sel[n];
        const float* pp = P + ((size_t)b*PNN + sidx)*3;
        float x = pp[0], y = pp[1], z = pp[2];
        float4 w0 = *(const float4*)&Wc[o];
        float4 w1 = *(const float4*)&Wc[HALFC + o];
        float4 w2 = *(const float4*)&Wc[2*HALFC + o];
        float4 bb = *(const float4*)&bc[o];
        float4 v;
        v.x = fmaf(x, w0.x, fmaf(y, w1.x, fmaf(z, w2.x, bb.x)));
        v.y = fmaf(x, w0.y, fmaf(y, w1.y, fmaf(z, w2.y, bb.y)));
        v.z = fmaf(x, w0.z, fmaf(y, w1.z, fmaf(z, w2.z, bb.z)));
        v.w = fmaf(x, w0.w, fmaf(y, w1.w, fmaf(z, w2.w, bb.w)));
        *(float4*)&g_comb[(size_t)n*CIN1 + HIDC + o] = v;
    }
}

// ---------------- GEMM: C[2048,384] = f(A[2048,K]) @ W[384,K]^T + bias -----
__global__ __launch_bounds__(256) void k_gemm(const float* __restrict__ Wt,
                                              const float* __restrict__ bias,
                                              int mode)
{
    const int BM=64, BN=64, BK=16;
    __shared__ float As[BK][BM];
    __shared__ float Bs[BK][BN];

    const float* A; float* C; const float* asc; const float* ash; int K;
    if (mode == 0){ A = g_comb; C = g_h1; asc = nullptr; ash = nullptr; K = CIN1; }
    else          { A = g_h1;   C = g_h2; asc = g_sc1;   ash = g_sh1;   K = HIDC; }

    int tx = threadIdx.x & 15;
    int ty = threadIdx.x >> 4;
    int m0 = blockIdx.y * BM;
    int n0 = blockIdx.x * BN;
    int lr = threadIdx.x >> 2;
    int lk = (threadIdx.x & 3) * 4;

    float acc[4][4];
#pragma unroll
    for (int i=0;i<4;i++)
#pragma unroll
        for (int j=0;j<4;j++) acc[i][j]=0.f;

    for (int k0 = 0; k0 < K; k0 += BK){
        float4 av = *(const float4*)&A[(size_t)(m0+lr)*K + k0 + lk];
        if (asc){
            float4 sv = *(const float4*)&asc[k0+lk];
            float4 hv = *(const float4*)&ash[k0+lk];
            av.x = fmaxf(fmaf(av.x, sv.x, hv.x), 0.f);
            av.y = fmaxf(fmaf(av.y, sv.y, hv.y), 0.f);
            av.z = fmaxf(fmaf(av.z, sv.z, hv.z), 0.f);
            av.w = fmaxf(fmaf(av.w, sv.w, hv.w), 0.f);
        }
        float4 bv = *(const float4*)&Wt[(size_t)(n0+lr)*K + k0 + lk];
        As[lk+0][lr]=av.x; As[lk+1][lr]=av.y; As[lk+2][lr]=av.z; As[lk+3][lr]=av.w;
        Bs[lk+0][lr]=bv.x; Bs[lk+1][lr]=bv.y; Bs[lk+2][lr]=bv.z; Bs[lk+3][lr]=bv.w;
        __syncthreads();
#pragma unroll
        for (int kk = 0; kk < BK; kk++){
            float4 a = *(const float4*)&As[kk][ty*4];
            float4 b = *(const float4*)&Bs[kk][tx*4];
            acc[0][0]=fmaf(a.x,b.x,acc[0][0]); acc[0][1]=fmaf(a.x,b.y,acc[0][1]);
            acc[0][2]=fmaf(a.x,b.z,acc[0][2]); acc[0][3]=fmaf(a.x,b.w,acc[0][3]);
            acc[1][0]=fmaf(a.y,b.x,acc[1][0]); acc[1][1]=fmaf(a.y,b.y,acc[1][1]);
            acc[1][2]=fmaf(a.y,b.z,acc[1][2]); acc[1][3]=fmaf(a.y,b.w,acc[1][3]);
            acc[2][0]=fmaf(a.z,b.x,acc[2][0]); acc[2][1]=fmaf(a.z,b.y,acc[2][1]);
            acc[2][2]=fmaf(a.z,b.z,acc[2][2]); acc[2][3]=fmaf(a.z,b.w,acc[2][3]);
            acc[3][0]=fmaf(a.w,b.x,acc[3][0]); acc[3][1]=fmaf(a.w,b.y,acc[3][1]);
            acc[3][2]=fmaf(a.w,b.z,acc[3][2]); acc[3][3]=fmaf(a.w,b.w,acc[3][3]);
        }
        __syncthreads();
    }
    float4 bb = *(const float4*)&bias[n0 + tx*4];
#pragma unroll
    for (int i = 0; i < 4; i++){
        float4 o;
        o.x = acc[i][0] + bb.x; o.y = acc[i][1] + bb.y;
        o.z = acc[i][2] + bb.z; o.w = acc[i][3] + bb.w;
        *(float4*)&C[(size_t)(m0 + ty*4 + i)*HIDC + n0 + tx*4] = o;
    }
}

// ---------------- BN stats -> per-channel scale/shift ----------------------
__global__ void k_stats(const float* __restrict__ g, const float* __restrict__ be, int mode){
    const float* X = (mode == 0) ? g_h1 : g_h2;
    float* sc = (mode == 0) ? g_sc1 : g_sc2;
    float* sh = (mode == 0) ? g_sh1 : g_sh2;

    __shared__ float ssum[256], ssq[256];
    int cl = threadIdx.x & 31;
    int rg = threadIdx.x >> 5;
    int c  = blockIdx.x * 32 + cl;
    float s = 0.f, q = 0.f;
    for (int r = rg; r < MROWS; r += 8){
        float v = X[(size_t)r*HIDC + c];
        s += v; q = fmaf(v, v, q);
    }
    ssum[threadIdx.x] = s; ssq[threadIdx.x] = q;
    __syncthreads();
    if (rg == 0){
#pragma unroll
        for (int i = 1; i < 8; i++){ s += ssum[i*32 + cl]; q += ssq[i*32 + cl]; }
        float mean = s * (1.f/MROWS);
        float var  = q * (1.f/MROWS) - mean*mean;
        float sv   = g[c] * rsqrtf(var + EPSC);
        sc[c] = sv;
        sh[c] = fmaf(-mean, sv, be[c]);
    }
}

// ---------------- final: out = relu(bn2(h2)) -------------------------------
__global__ void k_final(float* __restrict__ out){
    int i = blockIdx.x * 256 + threadIdx.x;
    float4 v = ((const float4*)g_h2)[i];
    int c = (i*4) % HIDC;
    v.x = fmaxf(fmaf(v.x, g_sc2[c+0], g_sh2[c+0]), 0.f);
    v.y = fmaxf(fmaf(v.y, g_sc2[c+1], g_sh2[c+1]), 0.f);
    v.z = fmaxf(fmaf(v.z, g_sc2[c+2], g_sh2[c+2]), 0.f);
    v.w = fmaxf(fmaf(v.w, g_sc2[c+3], g_sh2[c+3]), 0.f);
    ((float4*)out)[i] = v;
}

// ---------------- launch ---------------------------------------------------
extern "C" void kernel_launch(void* const* d_in, const int* in_sizes, int n_in,
                              void* d_out, int out_size){
    (void)in_sizes; (void)n_in; (void)out_size;
    const float* p   = (const float*)d_in[0];
    const float* pf  = (const float*)d_in[2];
    const float* Wf  = (const float*)d_in[3];
    const float* bf  = (const float*)d_in[4];
    const float* Wc  = (const float*)d_in[5];
    const float* bc  = (const float*)d_in[6];
    const float* W1  = (const float*)d_in[7];
    const float* b1  = (const float*)d_in[8];
    const float* g1  = (const float*)d_in[9];
    const float* be1 = (const float*)d_in[10];
    const float* W2  = (const float*)d_in[11];
    const float* b2  = (const float*)d_in[12];
    const float* g2  = (const float*)d_in[13];
    const float* be2 = (const float*)d_in[14];
    float* out = (float*)d_out;

    k_gram<<<1, 192>>>(Wc);
    k_gf<<<BB, HIDC>>>(pf, Wf, bf);
    k_prep<<<BB, 1024>>>(p);
    k_fps6<<<2*BB, FPS_T>>>(p);            // 2-CTA cluster per batch
    k_comb<<<(MROWS*144)/256, 256>>>(p, Wc, bc);
    k_gemm<<<dim3(HIDC/64, MROWS/64), 256>>>(W1, b1, 0);
    k_stats<<<HIDC/32, 256>>>(g1, be1, 0);
    k_gemm<<<dim3(HIDC/64, MROWS/64), 256>>>(W2, b2, 1);
    k_stats<<<HIDC/32, 256>>>(g2, be2, 1);
    k_final<<<(MROWS*HIDC/4)/256, 256>>>(out);
}

// round 10
// speedup vs baseline: 1.0845x; 1.0845x over previous
#include <cuda_runtime.h>
#include <cstdint>

// Problem constants
#define BB    8
#define PNN   16384
#define NSS   256
#define KDIMC 512
#define HIDC  384
#define HALFC 192
#define CIN1  576            // HID + HALF
#define MROWS (BB*NSS)       // 2048
#define EPSC  1e-5f

// ---------------- scratch (device globals; no allocation allowed) ----------
__device__ float               g_L[6];                 // chol(G)
__device__ __align__(16) float g_gf[BB*HIDC];
__device__ int                 g_sel[BB*NSS];
__device__ __align__(16) float4 g_pts[BB*PNN];         // reordered u-coords
__device__ int                 g_oidx[BB*PNN];
__device__ __align__(16) float g_A0[HIDC];             // conv1 collapse coeffs
__device__ __align__(16) float g_A1[HIDC];
__device__ __align__(16) float g_A2[HIDC];
__device__ __align__(16) float g_A3[HIDC];
__device__ __align__(16) float g_gfc[BB*HIDC];
__device__ __align__(16) float g_h1[MROWS*HIDC];
__device__ __align__(16) float g_h2[MROWS*HIDC];
__device__ __align__(16) float g_psum[8*HIDC];
__device__ __align__(16) float g_psq[8*HIDC];
__device__ __align__(16) float g_sc1[HIDC];
__device__ __align__(16) float g_sh1[HIDC];
__device__ __align__(16) float g_sc2[HIDC];
__device__ __align__(16) float g_sh2[HIDC];

// ---------------- helpers ---------------------------------------------------
__device__ __forceinline__ unsigned fenc(float f){
    unsigned u = __float_as_uint(f);
    return u ^ (unsigned)(((int)u >> 31) | 0x80000000);
}
__device__ __forceinline__ float fdec(unsigned u){
    unsigned b = (u & 0x80000000u) ? (u ^ 0x80000000u) : ~u;
    return __uint_as_float(b);
}
__device__ __forceinline__ int morton3(int x, int y, int z){
    int m = 0;
#pragma unroll
    for (int i = 0; i < 3; i++)
        m |= ((x>>i&1)<<(3*i+2)) | ((y>>i&1)<<(3*i+1)) | ((z>>i&1)<<(3*i));
    return m;
}
__device__ __forceinline__ unsigned long long pk2(float lo, float hi){
    unsigned long long r;
    asm("mov.b64 %0, {%1, %2};" : "=l"(r) : "f"(lo), "f"(hi));
    return r;
}
__device__ __forceinline__ void upk2(unsigned long long v, float& lo, float& hi){
    asm("mov.b64 {%0, %1}, %2;" : "=f"(lo), "=f"(hi) : "l"(v));
}
__device__ __forceinline__ unsigned long long fma2(unsigned long long a,
                                                   unsigned long long b,
                                                   unsigned long long c){
    unsigned long long r;
    asm("fma.rn.f32x2 %0, %1, %2, %3;" : "=l"(r) : "l"(a), "l"(b), "l"(c));
    return r;
}
__device__ __forceinline__ unsigned long long add2(unsigned long long a,
                                                   unsigned long long b){
    unsigned long long r;
    asm("add.rn.f32x2 %0, %1, %2;" : "=l"(r) : "l"(a), "l"(b));
    return r;
}
__device__ __forceinline__ unsigned long long mul2(unsigned long long a,
                                                   unsigned long long b){
    unsigned long long r;
    asm("mul.rn.f32x2 %0, %1, %2;" : "=l"(r) : "l"(a), "l"(b));
    return r;
}

// ---------------- G = Wc @ Wc^T, then Cholesky ------------------------------
__global__ void k_gram(const float* __restrict__ Wc){
    __shared__ float sG[9];
    const int pa[6] = {0,0,0,1,1,2};
    const int pb[6] = {0,1,2,1,2,2};
    int w = threadIdx.x >> 5, lane = threadIdx.x & 31;
    if (w < 6){
        float s = 0.f;
        for (int k = lane; k < HALFC; k += 32)
            s = fmaf(Wc[pa[w]*HALFC + k], Wc[pb[w]*HALFC + k], s);
#pragma unroll
        for (int o = 16; o > 0; o >>= 1) s += __shfl_down_sync(0xffffffffu, s, o);
        if (lane == 0){ sG[pa[w]*3+pb[w]] = s; sG[pb[w]*3+pa[w]] = s; }
    }
    __syncthreads();
    if (threadIdx.x == 0){
        float G00=sG[0],G01=sG[1],G02=sG[2],G11=sG[4],G12=sG[5],G22=sG[8];
        float L00 = sqrtf(G00);
        float L10 = G01 / L00;
        float L20 = G02 / L00;
        float L11 = sqrtf(G11 - L10*L10);
        float L21 = (G12 - L10*L20) / L11;
        float L22 = sqrtf(G22 - L20*L20 - L21*L21);
        g_L[0]=L00; g_L[1]=L10; g_L[2]=L20; g_L[3]=L11; g_L[4]=L21; g_L[5]=L22;
    }
}

// ---------------- global_feat = pf @ W_feat + b_feat  (8 x 384) ------------
__global__ void k_gf(const float* __restrict__ pf, const float* __restrict__ Wf,
                     const float* __restrict__ bf){
    __shared__ float sp[KDIMC];
    int b = blockIdx.x, t = threadIdx.x;
    for (int k = t; k < KDIMC; k += blockDim.x) sp[k] = pf[b*KDIMC + k];
    __syncthreads();
    float acc = bf[t];
#pragma unroll 4
    for (int k = 0; k < KDIMC; k++)
        acc = fmaf(sp[k], Wf[k*HIDC + t], acc);
    g_gf[b*HIDC + t] = acc;
}

// ---------------- k_prep: u = L^T p, Morton counting sort ------------------
__global__ __launch_bounds__(1024) void k_prep(const float* __restrict__ P){
    __shared__ unsigned s_bb[6];
    __shared__ int s_hist[512];
    __shared__ int s_off[512];
    __shared__ int s_wsum[16];
    __shared__ float s_lo[3], s_iv[3];

    int b = blockIdx.x, t = threadIdx.x;
    int lane = t & 31;
    float L00=g_L[0],L10=g_L[1],L20=g_L[2],L11=g_L[3],L21=g_L[4],L22=g_L[5];
    const float* pb = P + (size_t)b*PNN*3;

    if (t < 3)            s_bb[t] = 0xFFFFFFFFu;
    else if (t < 6)       s_bb[t] = 0u;
    if (t < 512) s_hist[t] = 0;
    __syncthreads();

    float mn[3] = {1e30f,1e30f,1e30f}, mx[3] = {-1e30f,-1e30f,-1e30f};
#pragma unroll
    for (int k = 0; k < 16; k++){
        int idx = t + k*1024;
        float px=pb[idx*3+0], py=pb[idx*3+1], pz=pb[idx*3+2];
        float u0 = fmaf(L00,px, fmaf(L10,py, L20*pz));
        float u1 = fmaf(L11,py, L21*pz);
        float u2 = L22*pz;
        mn[0]=fminf(mn[0],u0); mx[0]=fmaxf(mx[0],u0);
        mn[1]=fminf(mn[1],u1); mx[1]=fmaxf(mx[1],u1);
        mn[2]=fminf(mn[2],u2); mx[2]=fmaxf(mx[2],u2);
    }
#pragma unroll
    for (int d = 0; d < 3; d++){
        unsigned emn = __reduce_min_sync(0xffffffffu, fenc(mn[d]));
        unsigned emx = __reduce_max_sync(0xffffffffu, fenc(mx[d]));
        if (lane == 0){ atomicMin(&s_bb[d], emn); atomicMax(&s_bb[3+d], emx); }
    }
    __syncthreads();
    if (t < 3){
        float lo = fdec(s_bb[t]), hi = fdec(s_bb[3+t]);
        s_lo[t] = lo;
        s_iv[t] = 8.0f / fmaxf(hi - lo, 1e-20f);
    }
    __syncthreads();

    float lo0=s_lo[0], lo1=s_lo[1], lo2=s_lo[2];
    float iv0=s_iv[0], iv1=s_iv[1], iv2=s_iv[2];
    int cell[16];
#pragma unroll
    for (int k = 0; k < 16; k++){
        int idx = t + k*1024;
        float px=pb[idx*3+0], py=pb[idx*3+1], pz=pb[idx*3+2];
        float u0 = fmaf(L00,px, fmaf(L10,py, L20*pz));
        float u1 = fmaf(L11,py, L21*pz);
        float u2 = L22*pz;
        int c0 = min(7, max(0, (int)((u0-lo0)*iv0)));
        int c1 = min(7, max(0, (int)((u1-lo1)*iv1)));
        int c2 = min(7, max(0, (int)((u2-lo2)*iv2)));
        cell[k] = morton3(c0, c1, c2);
        atomicAdd(&s_hist[cell[k]], 1);
    }
    __syncthreads();

    if (t < 512){
        int v = s_hist[t], inc = v;
#pragma unroll
        for (int o = 1; o < 32; o <<= 1){
            int n = __shfl_up_sync(0xffffffffu, inc, o);
            if (lane >= o) inc += n;
        }
        if (lane == 31) s_wsum[t >> 5] = inc;
        s_off[t] = inc - v;
    }
    __syncthreads();
    if (t < 16){
        int v = s_wsum[t], inc = v;
#pragma unroll
        for (int o = 1; o < 16; o <<= 1){
            int n = __shfl_up_sync(0xffffu, inc, o);
            if (t >= o) inc += n;
        }
        s_wsum[t] = inc - v;
    }
    __syncthreads();
    if (t < 512) s_off[t] += s_wsum[t >> 5];
    __syncthreads();

#pragma unroll
    for (int k = 0; k < 16; k++){
        int idx = t + k*1024;
        float px=pb[idx*3+0], py=pb[idx*3+1], pz=pb[idx*3+2];
        float u0 = fmaf(L00,px, fmaf(L10,py, L20*pz));
        float u1 = fmaf(L11,py, L21*pz);
        float u2 = L22*pz;
        int pos = atomicAdd(&s_off[cell[k]], 1);
        g_pts[b*PNN + pos]  = make_float4(u0, u1, u2, 0.f);
        g_oidx[b*PNN + pos] = idx;
    }
}

// ---------------- FPS v5 (proven 242us): one barrier/step, f32x2 ----------
#define FPS_T 1024
#define FPS_K 16
#define SM_DIST 0
#define SM_Z    16384
#define SM_O    32768
#define SM_SLOT 49152            // u64[2][32] -> 128 floats
#define FPS_SMEM_FLOATS (49152 + 128)

__global__ __launch_bounds__(FPS_T, 1) void k_fps5(const float* __restrict__ P){
    extern __shared__ float sm[];
    float* smd = sm + SM_DIST;
    float* smz = sm + SM_Z;
    int*   smo = (int*)(sm + SM_O);
    unsigned long long* slot = (unsigned long long*)(sm + SM_SLOT); // [2][32]

    const int t = threadIdx.x, lane = t & 31, wid = t >> 5;
    const int b = blockIdx.x;
    const float4* gp = g_pts + (size_t)b*PNN;

    float uxs[FPS_K], uys[FPS_K];
    float bl0=1e30f, bl1=1e30f, bl2=1e30f, bh0=-1e30f, bh1=-1e30f, bh2=-1e30f;
#pragma unroll
    for (int k = 0; k < FPS_K; k++){
        float4 v = gp[t*FPS_K + k];
        uxs[k] = v.x; uys[k] = v.y;
        int swo = (wid<<9) + ((k>>2)<<7) + (lane<<2) + (k&3);
        smz[swo] = v.z;
        smd[swo] = 1e10f;
        smo[swo] = g_oidx[b*PNN + t*FPS_K + k];
        bl0=fminf(bl0,v.x); bh0=fmaxf(bh0,v.x);
        bl1=fminf(bl1,v.y); bh1=fmaxf(bh1,v.y);
        bl2=fminf(bl2,v.z); bh2=fmaxf(bh2,v.z);
    }
    unsigned long long X2[8], Y2[8];
#pragma unroll
    for (int p = 0; p < 8; p++){
        X2[p] = pk2(uxs[2*p], uxs[2*p+1]);
        Y2[p] = pk2(uys[2*p], uys[2*p+1]);
    }
    bl0 = fdec(__reduce_min_sync(0xffffffffu, fenc(bl0)));
    bl1 = fdec(__reduce_min_sync(0xffffffffu, fenc(bl1)));
    bl2 = fdec(__reduce_min_sync(0xffffffffu, fenc(bl2)));
    bh0 = fdec(__reduce_max_sync(0xffffffffu, fenc(bh0)));
    bh1 = fdec(__reduce_max_sync(0xffffffffu, fenc(bh1)));
    bh2 = fdec(__reduce_max_sync(0xffffffffu, fenc(bh2)));

    const float* p0 = P + (size_t)b*PNN*3;
    float px0=p0[0], py0=p0[1], pz0=p0[2];
    float cx = fmaf(g_L[0],px0, fmaf(g_L[1],py0, g_L[2]*pz0));
    float cy = fmaf(g_L[3],py0, g_L[4]*pz0);
    float cz = g_L[5]*pz0;
    if (t == 0) g_sel[b*NSS] = 0;
    __syncthreads();

    unsigned            wub  = 0xFFFFFFFFu;
    unsigned long long  wkey = 0ull;

    for (int j = 0; j < NSS-1; j++){
        float e0 = fmaxf(fmaxf(bl0-cx, cx-bh0), 0.f);
        float e1 = fmaxf(fmaxf(bl1-cy, cy-bh1), 0.f);
        float e2 = fmaxf(fmaxf(bl2-cz, cz-bh2), 0.f);
        float lb = fmaf(e0,e0, fmaf(e1,e1, e2*e2));

        if (__float_as_uint(lb) < wub){
            unsigned long long mcx2 = pk2(-cx,-cx);
            unsigned long long mcy2 = pk2(-cy,-cy);
            unsigned long long mcz2 = pk2(-cz,-cz);
            float gm[4]; float ub;
#pragma unroll
            for (int g = 0; g < 4; g++){
                int swo = (wid<<9) + (g<<7) + (lane<<2);
                ulonglong2 z2 = *(ulonglong2*)(smz + swo);
                float4 dd = *(float4*)(smd + swo);
                unsigned long long ax = add2(X2[2*g],   mcx2);
                unsigned long long ay = add2(Y2[2*g],   mcy2);
                unsigned long long az = add2(z2.x,      mcz2);
                unsigned long long d2 = fma2(ax,ax, fma2(ay,ay, mul2(az,az)));
                float d0, d1; upk2(d2, d0, d1);
                dd.x = fminf(dd.x, d0); dd.y = fminf(dd.y, d1);
                ax = add2(X2[2*g+1], mcx2);
                ay = add2(Y2[2*g+1], mcy2);
                az = add2(z2.y,      mcz2);
                d2 = fma2(ax,ax, fma2(ay,ay, mul2(az,az)));
                upk2(d2, d0, d1);
                dd.z = fminf(dd.z, d0); dd.w = fminf(dd.w, d1);
                *(float4*)(smd + swo) = dd;
                gm[g] = fmaxf(fmaxf(dd.x,dd.y), fmaxf(dd.z,dd.w));
            }
            ub = fmaxf(fmaxf(gm[0],gm[1]), fmaxf(gm[2],gm[3]));
            wub = __reduce_max_sync(0xffffffffu, __float_as_uint(ub));

            unsigned cand = 0u;
            if (__float_as_uint(ub) == wub){
#pragma unroll
                for (int g = 0; g < 4; g++){
                    if (__float_as_uint(gm[g]) == wub){
                        int swo = (wid<<9) + (g<<7) + (lane<<2);
                        float4 dd = *(float4*)(smd + swo);
                        int4   oo = *(int4*)  (smo + swo);
                        unsigned rb = (unsigned)(t*FPS_K + g*4);
                        if (__float_as_uint(dd.x)==wub)
                            cand = max(cand, ((0x3FFFu-(unsigned)oo.x)<<14)|(rb+0));
                        if (__float_as_uint(dd.y)==wub)
                            cand = max(cand, ((0x3FFFu-(unsigned)oo.y)<<14)|(rb+1));
                        if (__float_as_uint(dd.z)==wub)
                            cand = max(cand, ((0x3FFFu-(unsigned)oo.z)<<14)|(rb+2));
                        if (__float_as_uint(dd.w)==wub)
                            cand = max(cand, ((0x3FFFu-(unsigned)oo.w)<<14)|(rb+3));
                    }
                }
            }
            unsigned wlo = __reduce_max_sync(0xffffffffu, cand);
            wkey = ((unsigned long long)wub << 32) | wlo;
        }
        if (lane == 0) slot[((j&1)<<5) + wid] = wkey;
        __syncthreads();

        unsigned long long kk = slot[((j&1)<<5) + lane];
        unsigned hi = (unsigned)(kk >> 32), lo = (unsigned)kk;
        unsigned gh = __reduce_max_sync(0xffffffffu, hi);
        unsigned gl = __reduce_max_sync(0xffffffffu, (hi==gh) ? lo : 0u);

        int r = (int)(gl & 0x3FFFu);
        float4 cp = gp[r];
        cx = cp.x; cy = cp.y; cz = cp.z;
        if (t == 0) g_sel[b*NSS + j + 1] = (int)(0x3FFFu - (gl >> 14));
    }
}

// ---------------- conv1 collapse precompute --------------------------------
// A_i[o] = sum_{c<192} Wc[i][c] * W1[o][384+c];  A3[o] = sum_c bc[c]*W1[o][384+c] + b1[o]
__global__ __launch_bounds__(192) void k_pre1(const float* __restrict__ Wc,
                                              const float* __restrict__ bc,
                                              const float* __restrict__ W1,
                                              const float* __restrict__ b1){
    __shared__ float sred[6][4];
    int o = blockIdx.x, c = threadIdx.x;
    int lane = c & 31, w = c >> 5;
    float w1v = W1[(size_t)o*CIN1 + HIDC + c];
    float s0 = Wc[c]           * w1v;
    float s1 = Wc[HALFC + c]   * w1v;
    float s2 = Wc[2*HALFC + c] * w1v;
    float s3 = bc[c]           * w1v;
#pragma unroll
    for (int off = 16; off > 0; off >>= 1){
        s0 += __shfl_down_sync(0xffffffffu, s0, off);
        s1 += __shfl_down_sync(0xffffffffu, s1, off);
        s2 += __shfl_down_sync(0xffffffffu, s2, off);
        s3 += __shfl_down_sync(0xffffffffu, s3, off);
    }
    if (lane == 0){ sred[w][0]=s0; sred[w][1]=s1; sred[w][2]=s2; sred[w][3]=s3; }
    __syncthreads();
    if (c == 0){
        float a0=0,a1=0,a2=0,a3=0;
#pragma unroll
        for (int i = 0; i < 6; i++){ a0+=sred[i][0]; a1+=sred[i][1]; a2+=sred[i][2]; a3+=sred[i][3]; }
        g_A0[o]=a0; g_A1[o]=a1; g_A2[o]=a2; g_A3[o]=a3+b1[o];
    }
}

// gfc[b][o] = sum_{c<384} gf[b][c] * W1[o][c]
__global__ __launch_bounds__(HIDC) void k_pre2(const float* __restrict__ W1){
    __shared__ float sg[HIDC];
    int b = blockIdx.x, o = threadIdx.x;
    sg[o] = g_gf[b*HIDC + o];
    __syncthreads();
    float acc = 0.f;
#pragma unroll 4
    for (int c = 0; c < HIDC; c++)
        acc = fmaf(sg[c], W1[(size_t)o*CIN1 + c], acc);
    g_gfc[b*HIDC + o] = acc;
}

// ---------------- h1 build: rank-4 update per selected point ---------------
__global__ __launch_bounds__(256) void k_h1(const float* __restrict__ P){
    int f = blockIdx.x * 256 + threadIdx.x;       // float4 idx, 2048*96 total
    int n = f / 96, c4 = (f % 96) * 4;
    int b = n >> 8;
    int sidx = g_sel[n];
    const float* pp = P + ((size_t)b*PNN + sidx)*3;
    float x = pp[0], y = pp[1], z = pp[2];
    float4 a0 = *(const float4*)&g_A0[c4];
    float4 a1 = *(const float4*)&g_A1[c4];
    float4 a2 = *(const float4*)&g_A2[c4];
    float4 a3 = *(const float4*)&g_A3[c4];
    float4 gc = *(const float4*)&g_gfc[b*HIDC + c4];
    float4 v;
    v.x = gc.x + fmaf(x,a0.x, fmaf(y,a1.x, fmaf(z,a2.x, a3.x)));
    v.y = gc.y + fmaf(x,a0.y, fmaf(y,a1.y, fmaf(z,a2.y, a3.y)));
    v.z = gc.z + fmaf(x,a0.z, fmaf(y,a1.z, fmaf(z,a2.z, a3.z)));
    v.w = gc.w + fmaf(x,a0.w, fmaf(y,a1.w, fmaf(z,a2.w, a3.w)));
    *(float4*)&g_h1[(size_t)n*HIDC + c4] = v;
}

// ---------------- BN stats: partial pass (96 blocks) + reduce --------------
__global__ __launch_bounds__(256) void k_statsp(int mode){
    const float* X = (mode == 0) ? g_h1 : g_h2;
    __shared__ float ssum[256], ssq[256];
    int cl = threadIdx.x & 31;
    int rg = threadIdx.x >> 5;                    // 0..7
    int c  = blockIdx.x * 32 + cl;
    int r0 = blockIdx.y * 256;
    float s = 0.f, q = 0.f;
    for (int r = r0 + rg; r < r0 + 256; r += 8){
        float v = X[(size_t)r*HIDC + c];
        s += v; q = fmaf(v, v, q);
    }
    ssum[threadIdx.x] = s; ssq[threadIdx.x] = q;
    __syncthreads();
    if (rg == 0){
#pragma unroll
        for (int i = 1; i < 8; i++){ s += ssum[i*32 + cl]; q += ssq[i*32 + cl]; }
        g_psum[blockIdx.y*HIDC + c] = s;
        g_psq [blockIdx.y*HIDC + c] = q;
    }
}
__global__ __launch_bounds__(HIDC) void k_statsr(const float* __restrict__ g,
                                                 const float* __restrict__ be,
                                                 int mode){
    int c = threadIdx.x;
    float s = 0.f, q = 0.f;
#pragma unroll
    for (int i = 0; i < 8; i++){
        s += g_psum[i*HIDC + c];
        q += g_psq [i*HIDC + c];
    }
    float mean = s * (1.f/MROWS);
    float var  = q * (1.f/MROWS) - mean*mean;
    float sv   = g[c] * rsqrtf(var + EPSC);
    float sh   = fmaf(-mean, sv, be[c]);
    if (mode == 0){ g_sc1[c] = sv; g_sh1[c] = sh; }
    else          { g_sc2[c] = sv; g_sh2[c] = sh; }
}

// ---------------- GEMM2: C=g_h2 = relu(bn1(g_h1)) @ W2^T + b2 --------------
__global__ __launch_bounds__(256) void k_gemm(const float* __restrict__ Wt,
                                              const float* __restrict__ bias)
{
    const int BM=64, BN=64, BK=16, K=HIDC;
    __shared__ float As[BK][BM];
    __shared__ float Bs[BK][BN];

    int tx = threadIdx.x & 15;
    int ty = threadIdx.x >> 4;
    int m0 = blockIdx.y * BM;
    int n0 = blockIdx.x * BN;
    int lr = threadIdx.x >> 2;
    int lk = (threadIdx.x & 3) * 4;

    float acc[4][4];
#pragma unroll
    for (int i=0;i<4;i++)
#pragma unroll
        for (int j=0;j<4;j++) acc[i][j]=0.f;

    for (int k0 = 0; k0 < K; k0 += BK){
        float4 av = *(const float4*)&g_h1[(size_t)(m0+lr)*K + k0 + lk];
        float4 sv = *(const float4*)&g_sc1[k0+lk];
        float4 hv = *(const float4*)&g_sh1[k0+lk];
        av.x = fmaxf(fmaf(av.x, sv.x, hv.x), 0.f);
        av.y = fmaxf(fmaf(av.y, sv.y, hv.y), 0.f);
        av.z = fmaxf(fmaf(av.z, sv.z, hv.z), 0.f);
        av.w = fmaxf(fmaf(av.w, sv.w, hv.w), 0.f);
        float4 bv = *(const float4*)&Wt[(size_t)(n0+lr)*K + k0 + lk];
        As[lk+0][lr]=av.x; As[lk+1][lr]=av.y; As[lk+2][lr]=av.z; As[lk+3][lr]=av.w;
        Bs[lk+0][lr]=bv.x; Bs[lk+1][lr]=bv.y; Bs[lk+2][lr]=bv.z; Bs[lk+3][lr]=bv.w;
        __syncthreads();
#pragma unroll
        for (int kk = 0; kk < BK; kk++){
            float4 a = *(const float4*)&As[kk][ty*4];
            float4 b = *(const float4*)&Bs[kk][tx*4];
            acc[0][0]=fmaf(a.x,b.x,acc[0][0]); acc[0][1]=fmaf(a.x,b.y,acc[0][1]);
            acc[0][2]=fmaf(a.x,b.z,acc[0][2]); acc[0][3]=fmaf(a.x,b.w,acc[0][3]);
            acc[1][0]=fmaf(a.y,b.x,acc[1][0]); acc[1][1]=fmaf(a.y,b.y,acc[1][1]);
            acc[1][2]=fmaf(a.y,b.z,acc[1][2]); acc[1][3]=fmaf(a.y,b.w,acc[1][3]);
            acc[2][0]=fmaf(a.z,b.x,acc[2][0]); acc[2][1]=fmaf(a.z,b.y,acc[2][1]);
            acc[2][2]=fmaf(a.z,b.z,acc[2][2]); acc[2][3]=fmaf(a.z,b.w,acc[2][3]);
            acc[3][0]=fmaf(a.w,b.x,acc[3][0]); acc[3][1]=fmaf(a.w,b.y,acc[3][1]);
            acc[3][2]=fmaf(a.w,b.z,acc[3][2]); acc[3][3]=fmaf(a.w,b.w,acc[3][3]);
        }
        __syncthreads();
    }
    float4 bb = *(const float4*)&bias[n0 + tx*4];
#pragma unroll
    for (int i = 0; i < 4; i++){
        float4 o;
        o.x = acc[i][0] + bb.x; o.y = acc[i][1] + bb.y;
        o.z = acc[i][2] + bb.z; o.w = acc[i][3] + bb.w;
        *(float4*)&g_h2[(size_t)(m0 + ty*4 + i)*HIDC + n0 + tx*4] = o;
    }
}

// ---------------- final: out = relu(bn2(h2)) -------------------------------
__global__ void k_final(float* __restrict__ out){
    int i = blockIdx.x * 256 + threadIdx.x;
    float4 v = ((const float4*)g_h2)[i];
    int c = (i*4) % HIDC;
    v.x = fmaxf(fmaf(v.x, g_sc2[c+0], g_sh2[c+0]), 0.f);
    v.y = fmaxf(fmaf(v.y, g_sc2[c+1], g_sh2[c+1]), 0.f);
    v.z = fmaxf(fmaf(v.z, g_sc2[c+2], g_sh2[c+2]), 0.f);
    v.w = fmaxf(fmaf(v.w, g_sc2[c+3], g_sh2[c+3]), 0.f);
    ((float4*)out)[i] = v;
}

// ---------------- launch ---------------------------------------------------
extern "C" void kernel_launch(void* const* d_in, const int* in_sizes, int n_in,
                              void* d_out, int out_size){
    (void)in_sizes; (void)n_in; (void)out_size;
    const float* p   = (const float*)d_in[0];
    const float* pf  = (const float*)d_in[2];
    const float* Wf  = (const float*)d_in[3];
    const float* bf  = (const float*)d_in[4];
    const float* Wc  = (const float*)d_in[5];
    const float* bc  = (const float*)d_in[6];
    const float* W1  = (const float*)d_in[7];
    const float* b1  = (const float*)d_in[8];
    const float* g1  = (const float*)d_in[9];
    const float* be1 = (const float*)d_in[10];
    const float* W2  = (const float*)d_in[11];
    const float* b2  = (const float*)d_in[12];
    const float* g2  = (const float*)d_in[13];
    const float* be2 = (const float*)d_in[14];
    float* out = (float*)d_out;

    cudaFuncSetAttribute(k_fps5, cudaFuncAttributeMaxDynamicSharedMemorySize,
                         FPS_SMEM_FLOATS * (int)sizeof(float));

    k_gram<<<1, 192>>>(Wc);
    k_gf<<<BB, HIDC>>>(pf, Wf, bf);
    k_pre1<<<HIDC, 192>>>(Wc, bc, W1, b1);           // independent of FPS
    k_pre2<<<BB, HIDC>>>(W1);
    k_prep<<<BB, 1024>>>(p);
    k_fps5<<<BB, FPS_T, FPS_SMEM_FLOATS * sizeof(float)>>>(p);
    k_h1<<<(MROWS*96)/256, 256>>>(p);
    k_statsp<<<dim3(HIDC/32, 8), 256>>>(0);
    k_statsr<<<1, HIDC>>>(g1, be1, 0);
    k_gemm<<<dim3(HIDC/64, MROWS/64), 256>>>(W2, b2);
    k_statsp<<<dim3(HIDC/32, 8), 256>>>(1);
    k_statsr<<<1, HIDC>>>(g2, be2, 1);
    k_final<<<(MROWS*HIDC/4)/256, 256>>>(out);
}

// round 11
// speedup vs baseline: 1.3129x; 1.2106x over previous
#include <cuda_runtime.h>
#include <cstdint>

// Problem constants
#define BB    8
#define PNN   16384
#define NSS   256
#define KDIMC 512
#define HIDC  384
#define HALFC 192
#define CIN1  576            // HID + HALF
#define MROWS (BB*NSS)       // 2048
#define EPSC  1e-5f

// ---------------- scratch (device globals; no allocation allowed) ----------
__device__ float               g_L[6];                 // chol(G)
__device__ __align__(16) float g_gf[BB*HIDC];
__device__ int                 g_sel[BB*NSS];
__device__ __align__(16) float4 g_pts[BB*PNN];         // reordered u-coords
__device__ int                 g_oidx[BB*PNN];
__device__ __align__(16) float g_A0[HIDC];             // conv1 collapse coeffs
__device__ __align__(16) float g_A1[HIDC];
__device__ __align__(16) float g_A2[HIDC];
__device__ __align__(16) float g_A3[HIDC];
__device__ __align__(16) float g_gfc[BB*HIDC];
__device__ __align__(16) float g_h1[MROWS*HIDC];
__device__ __align__(16) float g_h2[MROWS*HIDC];
__device__ __align__(16) float g_psum[8*HIDC];
__device__ __align__(16) float g_psq[8*HIDC];
__device__ __align__(16) float g_sc1[HIDC];
__device__ __align__(16) float g_sh1[HIDC];
__device__ __align__(16) float g_sc2[HIDC];
__device__ __align__(16) float g_sh2[HIDC];

// ---------------- helpers ---------------------------------------------------
__device__ __forceinline__ unsigned fenc(float f){
    unsigned u = __float_as_uint(f);
    return u ^ (unsigned)(((int)u >> 31) | 0x80000000);
}
__device__ __forceinline__ float fdec(unsigned u){
    unsigned b = (u & 0x80000000u) ? (u ^ 0x80000000u) : ~u;
    return __uint_as_float(b);
}
__device__ __forceinline__ int morton3(int x, int y, int z){
    int m = 0;
#pragma unroll
    for (int i = 0; i < 3; i++)
        m |= ((x>>i&1)<<(3*i+2)) | ((y>>i&1)<<(3*i+1)) | ((z>>i&1)<<(3*i));
    return m;
}
__device__ __forceinline__ unsigned long long pk2(float lo, float hi){
    unsigned long long r;
    asm("mov.b64 %0, {%1, %2};" : "=l"(r) : "f"(lo), "f"(hi));
    return r;
}
__device__ __forceinline__ void upk2(unsigned long long v, float& lo, float& hi){
    asm("mov.b64 {%0, %1}, %2;" : "=f"(lo), "=f"(hi) : "l"(v));
}
__device__ __forceinline__ unsigned long long fma2(unsigned long long a,
                                                   unsigned long long b,
                                                   unsigned long long c){
    unsigned long long r;
    asm("fma.rn.f32x2 %0, %1, %2, %3;" : "=l"(r) : "l"(a), "l"(b), "l"(c));
    return r;
}
__device__ __forceinline__ unsigned long long add2(unsigned long long a,
                                                   unsigned long long b){
    unsigned long long r;
    asm("add.rn.f32x2 %0, %1, %2;" : "=l"(r) : "l"(a), "l"(b));
    return r;
}
__device__ __forceinline__ unsigned long long mul2(unsigned long long a,
                                                   unsigned long long b){
    unsigned long long r;
    asm("mul.rn.f32x2 %0, %1, %2;" : "=l"(r) : "l"(a), "l"(b));
    return r;
}

// ---------------- G = Wc @ Wc^T, then Cholesky ------------------------------
__global__ void k_gram(const float* __restrict__ Wc){
    __shared__ float sG[9];
    const int pa[6] = {0,0,0,1,1,2};
    const int pb[6] = {0,1,2,1,2,2};
    int w = threadIdx.x >> 5, lane = threadIdx.x & 31;
    if (w < 6){
        float s = 0.f;
        for (int k = lane; k < HALFC; k += 32)
            s = fmaf(Wc[pa[w]*HALFC + k], Wc[pb[w]*HALFC + k], s);
#pragma unroll
        for (int o = 16; o > 0; o >>= 1) s += __shfl_down_sync(0xffffffffu, s, o);
        if (lane == 0){ sG[pa[w]*3+pb[w]] = s; sG[pb[w]*3+pa[w]] = s; }
    }
    __syncthreads();
    if (threadIdx.x == 0){
        float G00=sG[0],G01=sG[1],G02=sG[2],G11=sG[4],G12=sG[5],G22=sG[8];
        float L00 = sqrtf(G00);
        float L10 = G01 / L00;
        float L20 = G02 / L00;
        float L11 = sqrtf(G11 - L10*L10);
        float L21 = (G12 - L10*L20) / L11;
        float L22 = sqrtf(G22 - L20*L20 - L21*L21);
        g_L[0]=L00; g_L[1]=L10; g_L[2]=L20; g_L[3]=L11; g_L[4]=L21; g_L[5]=L22;
    }
}

// ---------------- global_feat = pf @ W_feat + b_feat  (8 x 384) ------------
__global__ void k_gf(const float* __restrict__ pf, const float* __restrict__ Wf,
                     const float* __restrict__ bf){
    __shared__ float sp[KDIMC];
    int b = blockIdx.x, t = threadIdx.x;
    for (int k = t; k < KDIMC; k += blockDim.x) sp[k] = pf[b*KDIMC + k];
    __syncthreads();
    float acc = bf[t];
#pragma unroll 4
    for (int k = 0; k < KDIMC; k++)
        acc = fmaf(sp[k], Wf[k*HIDC + t], acc);
    g_gf[b*HIDC + t] = acc;
}

// ---------------- k_prep: u = L^T p, Morton counting sort ------------------
__global__ __launch_bounds__(1024) void k_prep(const float* __restrict__ P){
    __shared__ unsigned s_bb[6];
    __shared__ int s_hist[512];
    __shared__ int s_off[512];
    __shared__ int s_wsum[16];
    __shared__ float s_lo[3], s_iv[3];

    int b = blockIdx.x, t = threadIdx.x;
    int lane = t & 31;
    float L00=g_L[0],L10=g_L[1],L20=g_L[2],L11=g_L[3],L21=g_L[4],L22=g_L[5];
    const float* pb = P + (size_t)b*PNN*3;

    if (t < 3)            s_bb[t] = 0xFFFFFFFFu;
    else if (t < 6)       s_bb[t] = 0u;
    if (t < 512) s_hist[t] = 0;
    __syncthreads();

    float mn[3] = {1e30f,1e30f,1e30f}, mx[3] = {-1e30f,-1e30f,-1e30f};
#pragma unroll
    for (int k = 0; k < 16; k++){
        int idx = t + k*1024;
        float px=pb[idx*3+0], py=pb[idx*3+1], pz=pb[idx*3+2];
        float u0 = fmaf(L00,px, fmaf(L10,py, L20*pz));
        float u1 = fmaf(L11,py, L21*pz);
        float u2 = L22*pz;
        mn[0]=fminf(mn[0],u0); mx[0]=fmaxf(mx[0],u0);
        mn[1]=fminf(mn[1],u1); mx[1]=fmaxf(mx[1],u1);
        mn[2]=fminf(mn[2],u2); mx[2]=fmaxf(mx[2],u2);
    }
#pragma unroll
    for (int d = 0; d < 3; d++){
        unsigned emn = __reduce_min_sync(0xffffffffu, fenc(mn[d]));
        unsigned emx = __reduce_max_sync(0xffffffffu, fenc(mx[d]));
        if (lane == 0){ atomicMin(&s_bb[d], emn); atomicMax(&s_bb[3+d], emx); }
    }
    __syncthreads();
    if (t < 3){
        float lo = fdec(s_bb[t]), hi = fdec(s_bb[3+t]);
        s_lo[t] = lo;
        s_iv[t] = 8.0f / fmaxf(hi - lo, 1e-20f);
    }
    __syncthreads();

    float lo0=s_lo[0], lo1=s_lo[1], lo2=s_lo[2];
    float iv0=s_iv[0], iv1=s_iv[1], iv2=s_iv[2];
    int cell[16];
#pragma unroll
    for (int k = 0; k < 16; k++){
        int idx = t + k*1024;
        float px=pb[idx*3+0], py=pb[idx*3+1], pz=pb[idx*3+2];
        float u0 = fmaf(L00,px, fmaf(L10,py, L20*pz));
        float u1 = fmaf(L11,py, L21*pz);
        float u2 = L22*pz;
        int c0 = min(7, max(0, (int)((u0-lo0)*iv0)));
        int c1 = min(7, max(0, (int)((u1-lo1)*iv1)));
        int c2 = min(7, max(0, (int)((u2-lo2)*iv2)));
        cell[k] = morton3(c0, c1, c2);
        atomicAdd(&s_hist[cell[k]], 1);
    }
    __syncthreads();

    if (t < 512){
        int v = s_hist[t], inc = v;
#pragma unroll
        for (int o = 1; o < 32; o <<= 1){
            int n = __shfl_up_sync(0xffffffffu, inc, o);
            if (lane >= o) inc += n;
        }
        if (lane == 31) s_wsum[t >> 5] = inc;
        s_off[t] = inc - v;
    }
    __syncthreads();
    if (t < 16){
        int v = s_wsum[t], inc = v;
#pragma unroll
        for (int o = 1; o < 16; o <<= 1){
            int n = __shfl_up_sync(0xffffu, inc, o);
            if (t >= o) inc += n;
        }
        s_wsum[t] = inc - v;
    }
    __syncthreads();
    if (t < 512) s_off[t] += s_wsum[t >> 5];
    __syncthreads();

#pragma unroll
    for (int k = 0; k < 16; k++){
        int idx = t + k*1024;
        float px=pb[idx*3+0], py=pb[idx*3+1], pz=pb[idx*3+2];
        float u0 = fmaf(L00,px, fmaf(L10,py, L20*pz));
        float u1 = fmaf(L11,py, L21*pz);
        float u2 = L22*pz;
        int pos = atomicAdd(&s_off[cell[k]], 1);
        g_pts[b*PNN + pos]  = make_float4(u0, u1, u2, 0.f);
        g_oidx[b*PNN + pos] = idx;
    }
}

// ---------------- FPS v5 (proven 242us): one barrier/step, f32x2 ----------
#define FPS_T 1024
#define FPS_K 16
#define SM_DIST 0
#define SM_Z    16384
#define SM_O    32768
#define SM_SLOT 49152            // u64[2][32] -> 128 floats
#define FPS_SMEM_FLOATS (49152 + 128)

__global__ __launch_bounds__(FPS_T, 1) void k_fps5(const float* __restrict__ P){
    extern __shared__ float sm[];
    float* smd = sm + SM_DIST;
    float* smz = sm + SM_Z;
    int*   smo = (int*)(sm + SM_O);
    unsigned long long* slot = (unsigned long long*)(sm + SM_SLOT); // [2][32]

    const int t = threadIdx.x, lane = t & 31, wid = t >> 5;
    const int b = blockIdx.x;
    const float4* gp = g_pts + (size_t)b*PNN;

    float uxs[FPS_K], uys[FPS_K];
    float bl0=1e30f, bl1=1e30f, bl2=1e30f, bh0=-1e30f, bh1=-1e30f, bh2=-1e30f;
#pragma unroll
    for (int k = 0; k < FPS_K; k++){
        float4 v = gp[t*FPS_K + k];
        uxs[k] = v.x; uys[k] = v.y;
        int swo = (wid<<9) + ((k>>2)<<7) + (lane<<2) + (k&3);
        smz[swo] = v.z;
        smd[swo] = 1e10f;
        smo[swo] = g_oidx[b*PNN + t*FPS_K + k];
        bl0=fminf(bl0,v.x); bh0=fmaxf(bh0,v.x);
        bl1=fminf(bl1,v.y); bh1=fmaxf(bh1,v.y);
        bl2=fminf(bl2,v.z); bh2=fmaxf(bh2,v.z);
    }
    unsigned long long X2[8], Y2[8];
#pragma unroll
    for (int p = 0; p < 8; p++){
        X2[p] = pk2(uxs[2*p], uxs[2*p+1]);
        Y2[p] = pk2(uys[2*p], uys[2*p+1]);
    }
    bl0 = fdec(__reduce_min_sync(0xffffffffu, fenc(bl0)));
    bl1 = fdec(__reduce_min_sync(0xffffffffu, fenc(bl1)));
    bl2 = fdec(__reduce_min_sync(0xffffffffu, fenc(bl2)));
    bh0 = fdec(__reduce_max_sync(0xffffffffu, fenc(bh0)));
    bh1 = fdec(__reduce_max_sync(0xffffffffu, fenc(bh1)));
    bh2 = fdec(__reduce_max_sync(0xffffffffu, fenc(bh2)));

    const float* p0 = P + (size_t)b*PNN*3;
    float px0=p0[0], py0=p0[1], pz0=p0[2];
    float cx = fmaf(g_L[0],px0, fmaf(g_L[1],py0, g_L[2]*pz0));
    float cy = fmaf(g_L[3],py0, g_L[4]*pz0);
    float cz = g_L[5]*pz0;
    if (t == 0) g_sel[b*NSS] = 0;
    __syncthreads();

    unsigned            wub  = 0xFFFFFFFFu;
    unsigned long long  wkey = 0ull;

    for (int j = 0; j < NSS-1; j++){
        float e0 = fmaxf(fmaxf(bl0-cx, cx-bh0), 0.f);
        float e1 = fmaxf(fmaxf(bl1-cy, cy-bh1), 0.f);
        float e2 = fmaxf(fmaxf(bl2-cz, cz-bh2), 0.f);
        float lb = fmaf(e0,e0, fmaf(e1,e1, e2*e2));

        if (__float_as_uint(lb) < wub){
            unsigned long long mcx2 = pk2(-cx,-cx);
            unsigned long long mcy2 = pk2(-cy,-cy);
            unsigned long long mcz2 = pk2(-cz,-cz);
            float gm[4]; float ub;
#pragma unroll
            for (int g = 0; g < 4; g++){
                int swo = (wid<<9) + (g<<7) + (lane<<2);
                ulonglong2 z2 = *(ulonglong2*)(smz + swo);
                float4 dd = *(float4*)(smd + swo);
                unsigned long long ax = add2(X2[2*g],   mcx2);
                unsigned long long ay = add2(Y2[2*g],   mcy2);
                unsigned long long az = add2(z2.x,      mcz2);
                unsigned long long d2 = fma2(ax,ax, fma2(ay,ay, mul2(az,az)));
                float d0, d1; upk2(d2, d0, d1);
                dd.x = fminf(dd.x, d0); dd.y = fminf(dd.y, d1);
                ax = add2(X2[2*g+1], mcx2);
                ay = add2(Y2[2*g+1], mcy2);
                az = add2(z2.y,      mcz2);
                d2 = fma2(ax,ax, fma2(ay,ay, mul2(az,az)));
                upk2(d2, d0, d1);
                dd.z = fminf(dd.z, d0); dd.w = fminf(dd.w, d1);
                *(float4*)(smd + swo) = dd;
                gm[g] = fmaxf(fmaxf(dd.x,dd.y), fmaxf(dd.z,dd.w));
            }
            ub = fmaxf(fmaxf(gm[0],gm[1]), fmaxf(gm[2],gm[3]));
            wub = __reduce_max_sync(0xffffffffu, __float_as_uint(ub));

            unsigned cand = 0u;
            if (__float_as_uint(ub) == wub){
#pragma unroll
                for (int g = 0; g < 4; g++){
                    if (__float_as_uint(gm[g]) == wub){
                        int swo = (wid<<9) + (g<<7) + (lane<<2);
                        float4 dd = *(float4*)(smd + swo);
                        int4   oo = *(int4*)  (smo + swo);
                        unsigned rb = (unsigned)(t*FPS_K + g*4);
                        if (__float_as_uint(dd.x)==wub)
                            cand = max(cand, ((0x3FFFu-(unsigned)oo.x)<<14)|(rb+0));
                        if (__float_as_uint(dd.y)==wub)
                            cand = max(cand, ((0x3FFFu-(unsigned)oo.y)<<14)|(rb+1));
                        if (__float_as_uint(dd.z)==wub)
                            cand = max(cand, ((0x3FFFu-(unsigned)oo.z)<<14)|(rb+2));
                        if (__float_as_uint(dd.w)==wub)
                            cand = max(cand, ((0x3FFFu-(unsigned)oo.w)<<14)|(rb+3));
                    }
                }
            }
            unsigned wlo = __reduce_max_sync(0xffffffffu, cand);
            wkey = ((unsigned long long)wub << 32) | wlo;
        }
        if (lane == 0) slot[((j&1)<<5) + wid] = wkey;
        __syncthreads();

        unsigned long long kk = slot[((j&1)<<5) + lane];
        unsigned hi = (unsigned)(kk >> 32), lo = (unsigned)kk;
        unsigned gh = __reduce_max_sync(0xffffffffu, hi);
        unsigned gl = __reduce_max_sync(0xffffffffu, (hi==gh) ? lo : 0u);

        int r = (int)(gl & 0x3FFFu);
        float4 cp = gp[r];
        cx = cp.x; cy = cp.y; cz = cp.z;
        if (t == 0) g_sel[b*NSS + j + 1] = (int)(0x3FFFu - (gl >> 14));
    }
}

// ---------------- conv1 collapse precompute --------------------------------
// A_i[o] = sum_{c<192} Wc[i][c] * W1[o][384+c];  A3[o] = sum_c bc[c]*W1[o][384+c] + b1[o]
__global__ __launch_bounds__(192) void k_pre1(const float* __restrict__ Wc,
                                              const float* __restrict__ bc,
                                              const float* __restrict__ W1,
                                              const float* __restrict__ b1){
    __shared__ float sred[6][4];
    int o = blockIdx.x, c = threadIdx.x;
    int lane = c & 31, w = c >> 5;
    float w1v = W1[(size_t)o*CIN1 + HIDC + c];
    float s0 = Wc[c]           * w1v;
    float s1 = Wc[HALFC + c]   * w1v;
    float s2 = Wc[2*HALFC + c] * w1v;
    float s3 = bc[c]           * w1v;
#pragma unroll
    for (int off = 16; off > 0; off >>= 1){
        s0 += __shfl_down_sync(0xffffffffu, s0, off);
        s1 += __shfl_down_sync(0xffffffffu, s1, off);
        s2 += __shfl_down_sync(0xffffffffu, s2, off);
        s3 += __shfl_down_sync(0xffffffffu, s3, off);
    }
    if (lane == 0){ sred[w][0]=s0; sred[w][1]=s1; sred[w][2]=s2; sred[w][3]=s3; }
    __syncthreads();
    if (c == 0){
        float a0=0,a1=0,a2=0,a3=0;
#pragma unroll
        for (int i = 0; i < 6; i++){ a0+=sred[i][0]; a1+=sred[i][1]; a2+=sred[i][2]; a3+=sred[i][3]; }
        g_A0[o]=a0; g_A1[o]=a1; g_A2[o]=a2; g_A3[o]=a3+b1[o];
    }
}

// gfc[b][o] = sum_{c<384} gf[b][c] * W1[o][c]
// Warp-per-output: grid (48, BB), 256 thr. Lanes stride contiguously along the
// W1 row (coalesced); 12 iters; shfl reduce. Fixes the 77us strided-LDG k_pre2.
__global__ __launch_bounds__(256) void k_pre2(const float* __restrict__ W1){
    int b = blockIdx.y;
    int w = threadIdx.x >> 5, lane = threadIdx.x & 31;
    int o = blockIdx.x * 8 + w;
    const float* row = W1 + (size_t)o*CIN1;
    const float* gfb = g_gf + b*HIDC;
    float acc = 0.f;
#pragma unroll
    for (int it = 0; it < 12; it++){
        int c = it*32 + lane;
        acc = fmaf(gfb[c], row[c], acc);
    }
#pragma unroll
    for (int off = 16; off > 0; off >>= 1)
        acc += __shfl_down_sync(0xffffffffu, acc, off);
    if (lane == 0) g_gfc[b*HIDC + o] = acc;
}

// ---------------- h1 build: rank-4 update per selected point ---------------
__global__ __launch_bounds__(256) void k_h1(const float* __restrict__ P){
    int f = blockIdx.x * 256 + threadIdx.x;       // float4 idx, 2048*96 total
    int n = f / 96, c4 = (f % 96) * 4;
    int b = n >> 8;
    int sidx = g_sel[n];
    const float* pp = P + ((size_t)b*PNN + sidx)*3;
    float x = pp[0], y = pp[1], z = pp[2];
    float4 a0 = *(const float4*)&g_A0[c4];
    float4 a1 = *(const float4*)&g_A1[c4];
    float4 a2 = *(const float4*)&g_A2[c4];
    float4 a3 = *(const float4*)&g_A3[c4];
    float4 gc = *(const float4*)&g_gfc[b*HIDC + c4];
    float4 v;
    v.x = gc.x + fmaf(x,a0.x, fmaf(y,a1.x, fmaf(z,a2.x, a3.x)));
    v.y = gc.y + fmaf(x,a0.y, fmaf(y,a1.y, fmaf(z,a2.y, a3.y)));
    v.z = gc.z + fmaf(x,a0.z, fmaf(y,a1.z, fmaf(z,a2.z, a3.z)));
    v.w = gc.w + fmaf(x,a0.w, fmaf(y,a1.w, fmaf(z,a2.w, a3.w)));
    *(float4*)&g_h1[(size_t)n*HIDC + c4] = v;
}

// ---------------- BN stats: partial pass (96 blocks) + reduce --------------
__global__ __launch_bounds__(256) void k_statsp(int mode){
    const float* X = (mode == 0) ? g_h1 : g_h2;
    __shared__ float ssum[256], ssq[256];
    int cl = threadIdx.x & 31;
    int rg = threadIdx.x >> 5;                    // 0..7
    int c  = blockIdx.x * 32 + cl;
    int r0 = blockIdx.y * 256;
    float s = 0.f, q = 0.f;
    for (int r = r0 + rg; r < r0 + 256; r += 8){
        float v = X[(size_t)r*HIDC + c];
        s += v; q = fmaf(v, v, q);
    }
    ssum[threadIdx.x] = s; ssq[threadIdx.x] = q;
    __syncthreads();
    if (rg == 0){
#pragma unroll
        for (int i = 1; i < 8; i++){ s += ssum[i*32 + cl]; q += ssq[i*32 + cl]; }
        g_psum[blockIdx.y*HIDC + c] = s;
        g_psq [blockIdx.y*HIDC + c] = q;
    }
}
__global__ __launch_bounds__(HIDC) void k_statsr(const float* __restrict__ g,
                                                 const float* __restrict__ be,
                                                 int mode){
    int c = threadIdx.x;
    float s = 0.f, q = 0.f;
#pragma unroll
    for (int i = 0; i < 8; i++){
        s += g_psum[i*HIDC + c];
        q += g_psq [i*HIDC + c];
    }
    float mean = s * (1.f/MROWS);
    float var  = q * (1.f/MROWS) - mean*mean;
    float sv   = g[c] * rsqrtf(var + EPSC);
    float sh   = fmaf(-mean, sv, be[c]);
    if (mode == 0){ g_sc1[c] = sv; g_sh1[c] = sh; }
    else          { g_sc2[c] = sv; g_sh2[c] = sh; }
}

// ---------------- GEMM2: C=g_h2 = relu(bn1(g_h1)) @ W2^T + b2 --------------
__global__ __launch_bounds__(256) void k_gemm(const float* __restrict__ Wt,
                                              const float* __restrict__ bias)
{
    const int BM=64, BN=64, BK=16, K=HIDC;
    __shared__ float As[BK][BM];
    __shared__ float Bs[BK][BN];

    int tx = threadIdx.x & 15;
    int ty = threadIdx.x >> 4;
    int m0 = blockIdx.y * BM;
    int n0 = blockIdx.x * BN;
    int lr = threadIdx.x >> 2;
    int lk = (threadIdx.x & 3) * 4;

    float acc[4][4];
#pragma unroll
    for (int i=0;i<4;i++)
#pragma unroll
        for (int j=0;j<4;j++) acc[i][j]=0.f;

    for (int k0 = 0; k0 < K; k0 += BK){
        float4 av = *(const float4*)&g_h1[(size_t)(m0+lr)*K + k0 + lk];
        float4 sv = *(const float4*)&g_sc1[k0+lk];
        float4 hv = *(const float4*)&g_sh1[k0+lk];
        av.x = fmaxf(fmaf(av.x, sv.x, hv.x), 0.f);
        av.y = fmaxf(fmaf(av.y, sv.y, hv.y), 0.f);
        av.z = fmaxf(fmaf(av.z, sv.z, hv.z), 0.f);
        av.w = fmaxf(fmaf(av.w, sv.w, hv.w), 0.f);
        float4 bv = *(const float4*)&Wt[(size_t)(n0+lr)*K + k0 + lk];
        As[lk+0][lr]=av.x; As[lk+1][lr]=av.y; As[lk+2][lr]=av.z; As[lk+3][lr]=av.w;
        Bs[lk+0][lr]=bv.x; Bs[lk+1][lr]=bv.y; Bs[lk+2][lr]=bv.z; Bs[lk+3][lr]=bv.w;
        __syncthreads();
#pragma unroll
        for (int kk = 0; kk < BK; kk++){
            float4 a = *(const float4*)&As[kk][ty*4];
            float4 b = *(const float4*)&Bs[kk][tx*4];
            acc[0][0]=fmaf(a.x,b.x,acc[0][0]); acc[0][1]=fmaf(a.x,b.y,acc[0][1]);
            acc[0][2]=fmaf(a.x,b.z,acc[0][2]); acc[0][3]=fmaf(a.x,b.w,acc[0][3]);
            acc[1][0]=fmaf(a.y,b.x,acc[1][0]); acc[1][1]=fmaf(a.y,b.y,acc[1][1]);
            acc[1][2]=fmaf(a.y,b.z,acc[1][2]); acc[1][3]=fmaf(a.y,b.w,acc[1][3]);
            acc[2][0]=fmaf(a.z,b.x,acc[2][0]); acc[2][1]=fmaf(a.z,b.y,acc[2][1]);
            acc[2][2]=fmaf(a.z,b.z,acc[2][2]); acc[2][3]=fmaf(a.z,b.w,acc[2][3]);
            acc[3][0]=fmaf(a.w,b.x,acc[3][0]); acc[3][1]=fmaf(a.w,b.y,acc[3][1]);
            acc[3][2]=fmaf(a.w,b.z,acc[3][2]); acc[3][3]=fmaf(a.w,b.w,acc[3][3]);
        }
        __syncthreads();
    }
    float4 bb = *(const float4*)&bias[n0 + tx*4];
#pragma unroll
    for (int i = 0; i < 4; i++){
        float4 o;
        o.x = acc[i][0] + bb.x; o.y = acc[i][1] + bb.y;
        o.z = acc[i][2] + bb.z; o.w = acc[i][3] + bb.w;
        *(float4*)&g_h2[(size_t)(m0 + ty*4 + i)*HIDC + n0 + tx*4] = o;
    }
}

// ---------------- final: out = relu(bn2(h2)) -------------------------------
__global__ void k_final(float* __restrict__ out){
    int i = blockIdx.x * 256 + threadIdx.x;
    float4 v = ((const float4*)g_h2)[i];
    int c = (i*4) % HIDC;
    v.x = fmaxf(fmaf(v.x, g_sc2[c+0], g_sh2[c+0]), 0.f);
    v.y = fmaxf(fmaf(v.y, g_sc2[c+1], g_sh2[c+1]), 0.f);
    v.z = fmaxf(fmaf(v.z, g_sc2[c+2], g_sh2[c+2]), 0.f);
    v.w = fmaxf(fmaf(v.w, g_sc2[c+3], g_sh2[c+3]), 0.f);
    ((float4*)out)[i] = v;
}

// ---------------- launch ---------------------------------------------------
extern "C" void kernel_launch(void* const* d_in, const int* in_sizes, int n_in,
                              void* d_out, int out_size){
    (void)in_sizes; (void)n_in; (void)out_size;
    const float* p   = (const float*)d_in[0];
    const float* pf  = (const float*)d_in[2];
    const float* Wf  = (const float*)d_in[3];
    const float* bf  = (const float*)d_in[4];
    const float* Wc  = (const float*)d_in[5];
    const float* bc  = (const float*)d_in[6];
    const float* W1  = (const float*)d_in[7];
    const float* b1  = (const float*)d_in[8];
    const float* g1  = (const float*)d_in[9];
    const float* be1 = (const float*)d_in[10];
    const float* W2  = (const float*)d_in[11];
    const float* b2  = (const float*)d_in[12];
    const float* g2  = (const float*)d_in[13];
    const float* be2 = (const float*)d_in[14];
    float* out = (float*)d_out;

    cudaFuncSetAttribute(k_fps5, cudaFuncAttributeMaxDynamicSharedMemorySize,
                         FPS_SMEM_FLOATS * (int)sizeof(float));

    k_gram<<<1, 192>>>(Wc);
    k_gf<<<BB, HIDC>>>(pf, Wf, bf);
    k_pre1<<<HIDC, 192>>>(Wc, bc, W1, b1);
    k_pre2<<<dim3(HIDC/8, BB), 256>>>(W1);           // warp-per-row, coalesced
    k_prep<<<BB, 1024>>>(p);
    k_fps5<<<BB, FPS_T, FPS_SMEM_FLOATS * sizeof(float)>>>(p);
    k_h1<<<(MROWS*96)/256, 256>>>(p);
    k_statsp<<<dim3(HIDC/32, 8), 256>>>(0);
    k_statsr<<<1, HIDC>>>(g1, be1, 0);
    k_gemm<<<dim3(HIDC/64, MROWS/64), 256>>>(W2, b2);
    k_statsp<<<dim3(HIDC/32, 8), 256>>>(1);
    k_statsr<<<1, HIDC>>>(g2, be2, 1);
    k_final<<<(MROWS*HIDC/4)/256, 256>>>(out);
}